// round 16
// baseline (speedup 1.0000x reference)
#include <cuda_runtime.h>
#include <cuda_fp16.h>
#include <cstdint>

typedef uint32_t u32; typedef unsigned short u16;

#define DD 256
#define NCTA 296
#define NTHREADS 256

// ---- smem byte offsets (per CTA: 100 KB -> 2 CTAs/SM) ----
#define A_HI 0                      // [64][256] fp16 plane, swizzled, 32KB
#define BW_OFF 32768                // 3 slots x [256 n x 80B] fp16 k32 chunk
#define BROW 80
#define BPLANE (256 * BROW)         // 20480 per slot
#define BIAS_OFF (BW_OFF + 3 * BPLANE)      // 94208 (6*256 floats)
#define PV_OFF   (BIAS_OFF + 6 * 256 * 4)   // 100352 (512 floats)
#define SMEM_TOTAL (PV_OFF + 512 * 4)       // 102400 (100 KB)

// ---- device scratch ----
__device__ float d_p[2 * DD];
// [layer][k32-chunk][n][k-within-chunk]  (single fp16 plane)
__device__ __align__(16) __half d_Bw[6][8][256][32];

// ---- helpers ----
__device__ __forceinline__ u32 smem_u32(const void* p) {
    u32 a;
    asm("{ .reg .u64 t; cvta.to.shared.u64 t, %1; cvt.u32.u64 %0, t; }" : "=r"(a) : "l"(p));
    return a;
}
__device__ __forceinline__ float fast_tanh(float x) {
    float e, r;
    asm("ex2.approx.f32 %0, %1;" : "=f"(e) : "f"(x * 2.8853900817779268f));
    asm("rcp.approx.f32 %0, %1;" : "=f"(r) : "f"(e + 1.0f));
    return 1.0f - 2.0f * r;
}
// pack two floats as fp16x2 word
__device__ __forceinline__ u32 pack2h(float a, float b) {
    __half2 h = __floats2half2_rn(a, b);
    return *(u32*)&h;
}
// swizzled byte offset into the A plane: row stride 512B, 16B units XOR'd by row
__device__ __forceinline__ int aoff(int row, int col) {
    return row * 512 + ((((col >> 3) ^ (row & 7)) << 4) | ((col & 7) << 1));
}

#define LDSM4(r, addr) \
    asm volatile("ldmatrix.sync.aligned.m8n8.x4.shared.b16 {%0,%1,%2,%3}, [%4];" \
        : "=r"((r)[0]), "=r"((r)[1]), "=r"((r)[2]), "=r"((r)[3]) : "r"(addr))
#define MMA(d, a, b0, b1) \
    asm volatile("mma.sync.aligned.m16n8k16.row.col.f32.f16.f16.f32 " \
        "{%0,%1,%2,%3}, {%4,%5,%6,%7}, {%8,%9}, {%0,%1,%2,%3};" \
        : "+f"((d)[0]), "+f"((d)[1]), "+f"((d)[2]), "+f"((d)[3]) \
        : "r"((a)[0]), "r"((a)[1]), "r"((a)[2]), "r"((a)[3]), "r"(b0), "r"(b1))
#define CPASYNC16(dst, src) \
    asm volatile("cp.async.cg.shared.global [%0], [%1], 16;" :: "r"(dst), "l"(src))

// ---- fused prologue: weight fp16 reorder + p-vector ----
__global__ void prep(const float* __restrict__ w0, const float* __restrict__ w1,
                     const float* __restrict__ u1cw, const float* __restrict__ w2,
                     const float* __restrict__ u2cw, const float* __restrict__ wo,
                     const float* __restrict__ u1w, const float* __restrict__ u2w) {
    int b = blockIdx.x;
    if (b < 1536) {
        int L = b >> 8, n = b & 255, k = threadIdx.x;
        const float* W; bool direct;
        switch (L) {
            case 0: W = w0;   direct = false; break;
            case 1: W = w1;   direct = false; break;
            case 2: W = u1cw; direct = true;  break;
            case 3: W = w2;   direct = false; break;
            case 4: W = u2cw; direct = true;  break;
            default: W = wo;  direct = false; break;
        }
        // B[n][k]: layers computing h @ W^T read W[n][k]; direct (h @ W) reads W[k][n]
        float wv = direct ? W[k * DD + n] : W[n * DD + k];
        d_Bw[L][k >> 5][n][k & 31] = __float2half_rn(wv);
    } else {
        int t = (b - 1536) * 256 + threadIdx.x;    // 0..511
        const float* w = (t < DD) ? u1w : u2w;
        int j = t & (DD - 1);
        float prod = 1.0f / (float)DD;
        #pragma unroll
        for (int d = 0; d < 9; ++d)
            #pragma unroll
            for (int g = 0; g < 3; ++g) {
                float c = cosf(w[(d * DD + j) * DD + g]);
                prod *= c * c;
            }
        d_p[t] = prod;
    }
}

// ---- main kernel: 64-row tiles, single-pass fp16, k32 chunks, 2 CTAs/SM ----
__global__ void __launch_bounds__(NTHREADS, 2)
mlp_mma(const float* __restrict__ x,
        const float* __restrict__ b0, const float* __restrict__ b1,
        const float* __restrict__ u1cb, const float* __restrict__ b2,
        const float* __restrict__ u2cb, const float* __restrict__ bo,
        float* __restrict__ out)
{
    extern __shared__ __align__(1024) unsigned char sm[];
    float* smf = (float*)sm;
    const u32 smb = smem_u32(sm);
    const int tid = threadIdx.x, lane = tid & 31, wid = tid >> 5;
    const int wm = wid & 1, wn = wid >> 1;       // 2 m-tiles x 4 n-slabs
    const int mrow = wm * 32, ncol = wn * 64;

    // ---- stage biases and p ----
    {
        const float* bs[6] = { b0, b1, u1cb, b2, u2cb, bo };
        #pragma unroll
        for (int L = 0; L < 6; ++L) smf[BIAS_OFF / 4 + L * 256 + tid] = bs[L][tid];
        smf[PV_OFF / 4 + tid]       = d_p[tid];
        smf[PV_OFF / 4 + 256 + tid] = d_p[256 + tid];
    }

    // row range for this CTA (8-aligned, balanced over 296 CTAs)
    const int r0g = (int)(((long long)blockIdx.x << 15) / NCTA) & ~7;
    const int r1g = (int)(((long long)(blockIdx.x + 1) << 15) / NCTA) & ~7;

    // precomputed B ldmatrix base offsets for this warp (sub-chunk kk adds kk*32)
    u32 bad[4];
    #pragma unroll
    for (int nt2 = 0; nt2 < 4; ++nt2) {
        int n0 = ncol + nt2 * 16;
        int nrow = n0 + (lane & 7) + ((lane >> 4) << 3);
        bad[nt2] = nrow * BROW + (((lane >> 3) & 1) << 4);
    }

    // per-thread cp.async pieces: row n = tid, 4 x 16B (contiguous 64B source)
    const u32 cp_dst = tid * BROW;
    const int cp_src = tid * 64;

    for (int sub = 0; sub < 2; ++sub) {
        const int rbase = r0g + sub * 64;
        const int real  = sub ? (r1g - r0g - 64) : 64;   // sub1: 40..56

        // ---- prime ring: issue k32 chunks 0 and 1 ----
        #pragma unroll
        for (int pg = 0; pg < 2; ++pg) {
            u32 dst = smb + BW_OFF + pg * BPLANE + cp_dst;
            const char* src = (const char*)&d_Bw[0][pg][0][0] + cp_src;
            CPASYNC16(dst,      src);
            CPASYNC16(dst + 16, src + 16);
            CPASYNC16(dst + 32, src + 32);
            CPASYNC16(dst + 48, src + 48);
            asm volatile("cp.async.commit_group;");
        }

        // ---- load x tile (zero-padded), round to fp16 plane ----
        #pragma unroll 4
        for (int it = 0; it < 16; ++it) {
            int idx = it * NTHREADS + tid;           // 0..4095
            int row = idx >> 6, c0 = (idx & 63) * 4;
            float4 f = make_float4(0.f, 0.f, 0.f, 0.f);
            if (row < real)
                f = __ldg((const float4*)(x + (size_t)(rbase + row) * DD + c0));
            int off = aoff(row, c0);
            *(uint2*)(sm + A_HI + off) =
                make_uint2(pack2h(f.x, f.y), pack2h(f.z, f.w));
        }

        for (int L = 0; L < 6; ++L) {
            float acc[2][8][4];
            #pragma unroll
            for (int mt = 0; mt < 2; ++mt)
                #pragma unroll
                for (int j = 0; j < 8; ++j)
                    #pragma unroll
                    for (int q = 0; q < 4; ++q) acc[mt][j][q] = 0.f;

            for (int ck = 0; ck < 8; ++ck) {          // k32 chunks
                const int g = L * 8 + ck;             // global chunk 0..47
                if (g < 47) asm volatile("cp.async.wait_group 1;");
                else        asm volatile("cp.async.wait_group 0;");
                __syncthreads();
                // refill slot (g+2)%3 (retired by the barrier above)
                if (g + 2 < 48) {
                    const int g2 = g + 2;
                    const int nL = g2 / 8, nck = g2 & 7;
                    u32 dst = smb + BW_OFF + (g2 % 3) * BPLANE + cp_dst;
                    const char* src = (const char*)&d_Bw[nL][nck][0][0] + cp_src;
                    CPASYNC16(dst,      src);
                    CPASYNC16(dst + 16, src + 16);
                    CPASYNC16(dst + 32, src + 32);
                    CPASYNC16(dst + 48, src + 48);
                    asm volatile("cp.async.commit_group;");
                }

                // ---- two k16 sub-chunks, no barrier between ----
                const u32 bb = smb + BW_OFF + (g % 3) * BPLANE;
                #pragma unroll
                for (int kk = 0; kk < 2; ++kk) {
                    const int au = (ck * 2 + kk) * 2 + (lane >> 4);

                    u32 bh[16], ah[2][4];
                    #pragma unroll
                    for (int nt2 = 0; nt2 < 4; ++nt2)
                        LDSM4(&bh[nt2 * 4], bb + bad[nt2] + kk * 32);
                    #pragma unroll
                    for (int mt = 0; mt < 2; ++mt) {
                        int arow = mrow + mt * 16 + (lane & 15);
                        u32 abase = arow * 512 + (((au ^ (arow & 7)) << 4));
                        LDSM4(ah[mt], smb + A_HI + abase);
                    }
                    #pragma unroll
                    for (int mt = 0; mt < 2; ++mt)
                        #pragma unroll
                        for (int j = 0; j < 8; ++j)
                            MMA(acc[mt][j], ah[mt], bh[2 * j], bh[2 * j + 1]);
                }
            }

            __syncthreads();       // all compute done before A overwrite

            // ---- epilogue: bias + activation ----
            {
                const float* bias = smf + BIAS_OFF / 4 + L * 256;
                const float* pv   = smf + PV_OFF / 4 + ((L == 2) ? 0 : 256);
                const bool ut = (L == 2 || L == 4);
                const int r1 = mrow + (lane >> 2);
                #pragma unroll
                for (int mt = 0; mt < 2; ++mt) {
                    #pragma unroll
                    for (int j = 0; j < 8; ++j) {
                        int col = ncol + j * 8 + (lane & 3) * 2;
                        float bx = bias[col], by = bias[col + 1];
                        float v0 = acc[mt][j][0] + bx, v1 = acc[mt][j][1] + by;
                        float v2 = acc[mt][j][2] + bx, v3 = acc[mt][j][3] + by;
                        if (ut) {
                            float px = pv[col], py = pv[col + 1];
                            v0 = fast_tanh(v0 + px); v1 = fast_tanh(v1 + py);
                            v2 = fast_tanh(v2 + px); v3 = fast_tanh(v3 + py);
                        } else {
                            v0 = fmaxf(v0, 0.f); v1 = fmaxf(v1, 0.f);
                            v2 = fmaxf(v2, 0.f); v3 = fmaxf(v3, 0.f);
                        }
                        int ra = r1 + mt * 16, rb = ra + 8;   // 0..63
                        if (L == 5) {
                            if (ra < real) {
                                *(float2*)(out + (size_t)(rbase + ra) * DD + col)
                                    = make_float2(v0, v1);
                            }
                            if (rb < real) {
                                *(float2*)(out + (size_t)(rbase + rb) * DD + col)
                                    = make_float2(v2, v3);
                            }
                        } else {
                            // padded rows carry garbage but stay row-local; never stored
                            *(u32*)(sm + A_HI + aoff(ra, col)) = pack2h(v0, v1);
                            *(u32*)(sm + A_HI + aoff(rb, col)) = pack2h(v2, v3);
                        }
                    }
                }
            }
            // next chunk-loop's first __syncthreads orders epilogue writes vs reads
        }
    }
}

extern "C" void kernel_launch(void* const* d_in, const int* in_sizes, int n_in,
                              void* d_out, int out_size) {
    (void)in_sizes; (void)n_in; (void)out_size;
    const float* x    = (const float*)d_in[0];
    const float* w0   = (const float*)d_in[1];
    const float* b0   = (const float*)d_in[2];
    const float* w1   = (const float*)d_in[3];
    const float* b1   = (const float*)d_in[4];
    const float* u1w  = (const float*)d_in[5];
    const float* u1cw = (const float*)d_in[6];
    const float* u1cb = (const float*)d_in[7];
    const float* w2   = (const float*)d_in[8];
    const float* b2   = (const float*)d_in[9];
    const float* u2w  = (const float*)d_in[10];
    const float* u2cw = (const float*)d_in[11];
    const float* u2cb = (const float*)d_in[12];
    const float* wo   = (const float*)d_in[13];
    const float* bo   = (const float*)d_in[14];
    float* out = (float*)d_out;

    cudaFuncSetAttribute(mlp_mma, cudaFuncAttributeMaxDynamicSharedMemorySize, SMEM_TOTAL);

    prep<<<1538, 256>>>(w0, w1, u1cw, w2, u2cw, wo, u1w, u2w);
    mlp_mma<<<NCTA, NTHREADS, SMEM_TOTAL>>>(x, b0, b1, u1cb, b2, u2cb, bo, out);
}

// round 17
// speedup vs baseline: 1.3261x; 1.3261x over previous
#include <cuda_runtime.h>
#include <cuda_fp16.h>
#include <cstdint>

typedef uint32_t u32; typedef unsigned short u16;

#define DD 256
#define NCTA 148
#define NTHREADS 512

// ---- smem byte offsets (one CTA per SM) ----
#define A_HI 0                      // [128][256] fp16 plane, swizzled, 64KB
#define BW_OFF 65536                // 3 slots x [256 n x 48B] fp16 k16 chunk
#define BROW 48
#define BPLANE (256 * BROW)         // 12288 per slot
#define BIAS_OFF (BW_OFF + 3 * BPLANE)      // 102400 (6*256 floats)
#define PV_OFF   (BIAS_OFF + 6 * 256 * 4)   // 108544 (512 floats)
#define SMEM_TOTAL (PV_OFF + 512 * 4)       // 110592 (108 KB)

// ---- device scratch ----
__device__ float d_p[2 * DD];
// [layer][k16-chunk][n][k-within-chunk]  (single fp16 plane)
__device__ __align__(16) __half d_Bw[6][16][256][16];

// ---- helpers ----
__device__ __forceinline__ u32 smem_u32(const void* p) {
    u32 a;
    asm("{ .reg .u64 t; cvta.to.shared.u64 t, %1; cvt.u32.u64 %0, t; }" : "=r"(a) : "l"(p));
    return a;
}
__device__ __forceinline__ float fast_tanh(float x) {
    float e, r;
    asm("ex2.approx.f32 %0, %1;" : "=f"(e) : "f"(x * 2.8853900817779268f));
    asm("rcp.approx.f32 %0, %1;" : "=f"(r) : "f"(e + 1.0f));
    return 1.0f - 2.0f * r;
}
// pack two floats as fp16x2 word
__device__ __forceinline__ u32 pack2h(float a, float b) {
    __half2 h = __floats2half2_rn(a, b);
    return *(u32*)&h;
}
// swizzled byte offset into the A plane: row stride 512B, 16B units XOR'd by row
__device__ __forceinline__ int aoff(int row, int col) {
    return row * 512 + ((((col >> 3) ^ (row & 7)) << 4) | ((col & 7) << 1));
}

#define LDSM4(r, addr) \
    asm volatile("ldmatrix.sync.aligned.m8n8.x4.shared.b16 {%0,%1,%2,%3}, [%4];" \
        : "=r"((r)[0]), "=r"((r)[1]), "=r"((r)[2]), "=r"((r)[3]) : "r"(addr))
#define MMA(d, a, b0, b1) \
    asm volatile("mma.sync.aligned.m16n8k16.row.col.f32.f16.f16.f32 " \
        "{%0,%1,%2,%3}, {%4,%5,%6,%7}, {%8,%9}, {%0,%1,%2,%3};" \
        : "+f"((d)[0]), "+f"((d)[1]), "+f"((d)[2]), "+f"((d)[3]) \
        : "r"((a)[0]), "r"((a)[1]), "r"((a)[2]), "r"((a)[3]), "r"(b0), "r"(b1))
#define CPASYNC16(dst, src) \
    asm volatile("cp.async.cg.shared.global [%0], [%1], 16;" :: "r"(dst), "l"(src))

// ---- fused prologue: weight fp16 reorder + p-vector ----
__global__ void prep(const float* __restrict__ w0, const float* __restrict__ w1,
                     const float* __restrict__ u1cw, const float* __restrict__ w2,
                     const float* __restrict__ u2cw, const float* __restrict__ wo,
                     const float* __restrict__ u1w, const float* __restrict__ u2w) {
    int b = blockIdx.x;
    if (b < 1536) {
        int L = b >> 8, n = b & 255, k = threadIdx.x;
        const float* W; bool direct;
        switch (L) {
            case 0: W = w0;   direct = false; break;
            case 1: W = w1;   direct = false; break;
            case 2: W = u1cw; direct = true;  break;
            case 3: W = w2;   direct = false; break;
            case 4: W = u2cw; direct = true;  break;
            default: W = wo;  direct = false; break;
        }
        // B[n][k]: layers computing h @ W^T read W[n][k]; direct (h @ W) reads W[k][n]
        float wv = direct ? W[k * DD + n] : W[n * DD + k];
        d_Bw[L][k >> 4][n][k & 15] = __float2half_rn(wv);
    } else {
        int t = (b - 1536) * 256 + threadIdx.x;    // 0..511
        const float* w = (t < DD) ? u1w : u2w;
        int j = t & (DD - 1);
        float prod = 1.0f / (float)DD;
        #pragma unroll
        for (int d = 0; d < 9; ++d)
            #pragma unroll
            for (int g = 0; g < 3; ++g) {
                float c = cosf(w[(d * DD + j) * DD + g]);
                prod *= c * c;
            }
        d_p[t] = prod;
    }
}

// ---- main kernel: 128-row tiles, 512 threads, single-pass fp16 ----
__global__ void __launch_bounds__(NTHREADS, 1)
mlp_mma(const float* __restrict__ x,
        const float* __restrict__ b0, const float* __restrict__ b1,
        const float* __restrict__ u1cb, const float* __restrict__ b2,
        const float* __restrict__ u2cb, const float* __restrict__ bo,
        float* __restrict__ out)
{
    extern __shared__ __align__(1024) unsigned char sm[];
    float* smf = (float*)sm;
    const u32 smb = smem_u32(sm);
    const int tid = threadIdx.x, lane = tid & 31, wid = tid >> 5;
    const int wm = wid & 3, wn = wid >> 2;       // 4 m-chunks x 4 n-slabs
    const int mrow = wm * 32, ncol = wn * 64;

    // ---- stage biases and p ----
    if (tid < 256) {
        const float* bs[6] = { b0, b1, u1cb, b2, u2cb, bo };
        #pragma unroll
        for (int L = 0; L < 6; ++L) smf[BIAS_OFF / 4 + L * 256 + tid] = bs[L][tid];
        smf[PV_OFF / 4 + tid]       = d_p[tid];
        smf[PV_OFF / 4 + 256 + tid] = d_p[256 + tid];
    }

    // row range for this CTA (8-aligned, balanced over 148 CTAs)
    const int r0g = (int)(((long long)blockIdx.x << 15) / NCTA) & ~7;
    const int r1g = (int)(((long long)(blockIdx.x + 1) << 15) / NCTA) & ~7;

    // precomputed B ldmatrix base offsets for this warp
    u32 bad[4];
    #pragma unroll
    for (int nt2 = 0; nt2 < 4; ++nt2) {
        int n0 = ncol + nt2 * 16;
        int nrow = n0 + (lane & 7) + ((lane >> 4) << 3);
        bad[nt2] = nrow * BROW + (((lane >> 3) & 1) << 4);
    }

    // per-thread cp.async piece (512 x 16B per chunk over 512 threads = 1 each)
    const int cn = tid >> 1, cj = tid & 1;

    for (int sub = 0; sub < 2; ++sub) {
        const int rbase = r0g + sub * 128;
        const int H     = sub ? 96 : 128;
        const int real  = sub ? (r1g - r0g - 128) : 128;   // sub1: 88..96
        const bool act  = (sub == 0) | (wm < 3);

        // ---- prime ring: issue chunks 0 and 1 ----
        #pragma unroll
        for (int pg = 0; pg < 2; ++pg) {
            u32 dst = smb + BW_OFF + pg * BPLANE + cn * BROW + cj * 16;
            CPASYNC16(dst, (const char*)&d_Bw[0][pg][cn][cj * 8]);
            asm volatile("cp.async.commit_group;");
        }

        // ---- load x tile (zero-padded), round to fp16 plane ----
        {
            const int iters = (H * 64) / NTHREADS;   // 16 or 12
            for (int it = 0; it < iters; ++it) {
                int idx = it * NTHREADS + tid;
                int row = idx >> 6, c0 = (idx & 63) * 4;
                float4 f = make_float4(0.f, 0.f, 0.f, 0.f);
                if (row < real)
                    f = __ldg((const float4*)(x + (size_t)(rbase + row) * DD + c0));
                int off = aoff(row, c0);
                *(uint2*)(sm + A_HI + off) =
                    make_uint2(pack2h(f.x, f.y), pack2h(f.z, f.w));
            }
        }

        for (int L = 0; L < 6; ++L) {
            float acc[2][8][4];
            #pragma unroll
            for (int mt = 0; mt < 2; ++mt)
                #pragma unroll
                for (int j = 0; j < 8; ++j)
                    #pragma unroll
                    for (int q = 0; q < 4; ++q) acc[mt][j][q] = 0.f;

            for (int ck = 0; ck < 16; ++ck) {
                const int g = L * 16 + ck;
                if (g < 95) asm volatile("cp.async.wait_group 1;");
                else        asm volatile("cp.async.wait_group 0;");
                __syncthreads();
                // refill slot (g+2)%3 (retired by the barrier above)
                if (g + 2 < 96) {
                    const int g2 = g + 2;
                    const int nL = g2 >> 4, nck = g2 & 15;
                    u32 dst = smb + BW_OFF + (g2 % 3) * BPLANE + cn * BROW + cj * 16;
                    CPASYNC16(dst, (const char*)&d_Bw[nL][nck][cn][cj * 8]);
                    asm volatile("cp.async.commit_group;");
                }

                if (act) {
                    const u32 bb = smb + BW_OFF + (g % 3) * BPLANE;
                    const int au = ck * 2 + (lane >> 4);

                    u32 bh[16], ah[2][4];
                    #pragma unroll
                    for (int nt2 = 0; nt2 < 4; ++nt2)
                        LDSM4(&bh[nt2 * 4], bb + bad[nt2]);
                    #pragma unroll
                    for (int mt = 0; mt < 2; ++mt) {
                        int arow = mrow + mt * 16 + (lane & 15);
                        u32 abase = arow * 512 + (((au ^ (arow & 7)) << 4));
                        LDSM4(ah[mt], smb + A_HI + abase);
                    }
                    // single pass: A x B
                    #pragma unroll
                    for (int mt = 0; mt < 2; ++mt)
                        #pragma unroll
                        for (int j = 0; j < 8; ++j)
                            MMA(acc[mt][j], ah[mt], bh[2 * j], bh[2 * j + 1]);
                }
            }

            __syncthreads();       // all compute done before A overwrite

            // ---- epilogue: bias + activation ----
            if (act) {
                const float* bias = smf + BIAS_OFF / 4 + L * 256;
                const float* pv   = smf + PV_OFF / 4 + ((L == 2) ? 0 : 256);
                const bool ut = (L == 2 || L == 4);
                const int r1 = mrow + (lane >> 2);
                #pragma unroll
                for (int mt = 0; mt < 2; ++mt) {
                    #pragma unroll
                    for (int j = 0; j < 8; ++j) {
                        int col = ncol + j * 8 + (lane & 3) * 2;
                        float bx = bias[col], by = bias[col + 1];
                        float v0 = acc[mt][j][0] + bx, v1 = acc[mt][j][1] + by;
                        float v2 = acc[mt][j][2] + bx, v3 = acc[mt][j][3] + by;
                        if (ut) {
                            float px = pv[col], py = pv[col + 1];
                            v0 = fast_tanh(v0 + px); v1 = fast_tanh(v1 + py);
                            v2 = fast_tanh(v2 + px); v3 = fast_tanh(v3 + py);
                        } else {
                            v0 = fmaxf(v0, 0.f); v1 = fmaxf(v1, 0.f);
                            v2 = fmaxf(v2, 0.f); v3 = fmaxf(v3, 0.f);
                        }
                        int ra = r1 + mt * 16, rb = ra + 8;
                        if (L == 5) {
                            if (ra < real) {
                                *(float2*)(out + (size_t)(rbase + ra) * DD + col)
                                    = make_float2(v0, v1);
                            }
                            if (rb < real) {
                                *(float2*)(out + (size_t)(rbase + rb) * DD + col)
                                    = make_float2(v2, v3);
                            }
                        } else {
                            // padded rows carry garbage but stay row-local; never stored
                            *(u32*)(sm + A_HI + aoff(ra, col)) = pack2h(v0, v1);
                            *(u32*)(sm + A_HI + aoff(rb, col)) = pack2h(v2, v3);
                        }
                    }
                }
            }
            // next chunk-loop's first __syncthreads orders epilogue writes vs reads
        }
    }
}

extern "C" void kernel_launch(void* const* d_in, const int* in_sizes, int n_in,
                              void* d_out, int out_size) {
    (void)in_sizes; (void)n_in; (void)out_size;
    const float* x    = (const float*)d_in[0];
    const float* w0   = (const float*)d_in[1];
    const float* b0   = (const float*)d_in[2];
    const float* w1   = (const float*)d_in[3];
    const float* b1   = (const float*)d_in[4];
    const float* u1w  = (const float*)d_in[5];
    const float* u1cw = (const float*)d_in[6];
    const float* u1cb = (const float*)d_in[7];
    const float* w2   = (const float*)d_in[8];
    const float* b2   = (const float*)d_in[9];
    const float* u2w  = (const float*)d_in[10];
    const float* u2cw = (const float*)d_in[11];
    const float* u2cb = (const float*)d_in[12];
    const float* wo   = (const float*)d_in[13];
    const float* bo   = (const float*)d_in[14];
    float* out = (float*)d_out;

    cudaFuncSetAttribute(mlp_mma, cudaFuncAttributeMaxDynamicSharedMemorySize, SMEM_TOTAL);

    prep<<<1538, 256>>>(w0, w1, u1cw, w2, u2cw, wo, u1w, u2w);
    mlp_mma<<<NCTA, NTHREADS, SMEM_TOTAL>>>(x, b0, b1, u1cb, b2, u2cb, bo, out);
}